// round 13
// baseline (speedup 1.0000x reference)
#include <cuda_runtime.h>
#include <cuda_fp16.h>
#include <math.h>
#include <stdint.h>

// ---------------- problem constants ----------------
#define T_SEQ   2048
#define BATCH   2
#define D_EMB   1024
#define NHEAD   16
#define HDIM    64
#define BNECK   800
#define LOG2E   1.4426950408889634f
#define SCAL2   (0.125f * LOG2E)     // folded into Q projection; softmax uses exp2
#define TPAD    2176                 // 17 chunks * 128 keys; prefix row at 2048
#define XS      (4096 * 1024)        // one input-plane slot (elements)

// ---------------- scratch (device globals; zero-initialized) ----------------
__device__ float g_h[BATCH * BNECK];

// single fp16 planes. g_x slots: 0=query/ctx, 1=key, 2=value
__device__ __half g_x[3 * XS];
__device__ __half g_w[4][1024 * 1024];                 // wq,wk,wv,wo
__device__ __half g_q [BATCH * NHEAD * T_SEQ * HDIM];
__device__ __half g_k [BATCH * NHEAD * TPAD * HDIM];   // rows 2049.. stay zero
__device__ __half g_v [BATCH * NHEAD * TPAD * HDIM];

// ---------------- helpers ----------------
__device__ __forceinline__ uint32_t smem_u32(const void* p) {
    uint32_t a;
    asm("{ .reg .u64 t; cvta.to.shared.u64 t, %1; cvt.u32.u64 %0, t; }" : "=r"(a) : "l"(p));
    return a;
}
__device__ __forceinline__ void ldsm4(uint32_t* r, uint32_t a) {
    asm volatile("ldmatrix.sync.aligned.m8n8.x4.shared.b16 {%0,%1,%2,%3}, [%4];"
                 : "=r"(r[0]), "=r"(r[1]), "=r"(r[2]), "=r"(r[3]) : "r"(a));
}
__device__ __forceinline__ void ldsm4t(uint32_t* r, uint32_t a) {
    asm volatile("ldmatrix.sync.aligned.m8n8.x4.trans.shared.b16 {%0,%1,%2,%3}, [%4];"
                 : "=r"(r[0]), "=r"(r[1]), "=r"(r[2]), "=r"(r[3]) : "r"(a));
}
__device__ __forceinline__ void mma16816(float* c, const uint32_t* a, uint32_t b0, uint32_t b1) {
    asm volatile("mma.sync.aligned.m16n8k16.row.col.f32.f16.f16.f32 "
                 "{%0,%1,%2,%3}, {%4,%5,%6,%7}, {%8,%9}, {%0,%1,%2,%3};"
                 : "+f"(c[0]), "+f"(c[1]), "+f"(c[2]), "+f"(c[3])
                 : "r"(a[0]), "r"(a[1]), "r"(a[2]), "r"(a[3]), "r"(b0), "r"(b1));
}
__device__ __forceinline__ void cpa16(uint32_t sdst, const void* gsrc) {
    asm volatile("cp.async.cg.shared.global [%0], [%1], 16;" :: "r"(sdst), "l"(gsrc));
}
#define CP_COMMIT() asm volatile("cp.async.commit_group;" ::: "memory")
#define CP_WAIT1()  asm volatile("cp.async.wait_group 1;" ::: "memory")
#define CP_WAIT0()  asm volatile("cp.async.wait_group 0;" ::: "memory")

__device__ __forceinline__ float ex2(float x) {
    float y;
    asm("ex2.approx.ftz.f32 %0, %1;" : "=f"(y) : "f"(x));
    return y;
}

// 128B-row swizzle (8 chunks of 16B per row)
__device__ __forceinline__ uint32_t swz128(int r, int cc) {
    return (uint32_t)(r * 128 + ((cc ^ (r & 7)) << 4));
}

__device__ __forceinline__ float warp_reduce(float v) {
    #pragma unroll
    for (int o = 16; o; o >>= 1) v += __shfl_xor_sync(0xffffffffu, v, o);
    return v;
}

// ---------------- merged conversion: 3 inputs + 4 weights ----------------
__global__ void conv_all_kernel(const float* __restrict__ q, const float* __restrict__ k,
                                const float* __restrict__ v, const float* __restrict__ w0,
                                const float* __restrict__ w1, const float* __restrict__ w2,
                                const float* __restrict__ w3) {
    int slot = blockIdx.y;
    const float* src;
    __half* dstp;
    if (slot < 3) {
        src = (slot == 0) ? q : (slot == 1) ? k : v;
        dstp = g_x + (size_t)slot * XS;
    } else {
        if (blockIdx.x >= 1024) return;
        int ws = slot - 3;
        src = (ws == 0) ? w0 : (ws == 1) ? w1 : (ws == 2) ? w2 : w3;
        dstp = g_w[ws];
    }
    int i = blockIdx.x * 256 + threadIdx.x;
    float4 val = ((const float4*)src)[i];
    __half2* pd = (__half2*)dstp;
    pd[i * 2 + 0] = __half2(__float2half_rn(val.x), __float2half_rn(val.y));
    pd[i * 2 + 1] = __half2(__float2half_rn(val.z), __float2half_rn(val.w));
}

// ---------------- prefix MLP (warp-per-output) ----------------
// grid (100, BATCH), block 256 (8 warps); warp w computes j = bx*8+w
__global__ void prefix_h_kernel(const float* __restrict__ wte,
                                const float* __restrict__ ct_w1,
                                const float* __restrict__ ct_b1,
                                const int*   __restrict__ lang) {
    int wid = threadIdx.x >> 5, lane = threadIdx.x & 31;
    int j = blockIdx.x * 8 + wid;
    int b = blockIdx.y;
    int c = lang[b];
    const float* w = ct_w1 + ((size_t)c * BNECK + j) * D_EMB;
    const float* e = wte + (size_t)c * D_EMB;
    float s = 0.f;
    #pragma unroll
    for (int it = 0; it < 8; it++) {
        float4 wv = *(const float4*)(w + (lane + it * 32) * 4);
        float4 ev = *(const float4*)(e + (lane + it * 32) * 4);
        s += wv.x * ev.x + wv.y * ev.y + wv.z * ev.z + wv.w * ev.w;
    }
    s = warp_reduce(s);
    if (lane == 0)
        g_h[b * BNECK + j] = tanhf(s + ct_b1[c * BNECK + j]);
}

// grid (256, BATCH), block 256; warp w computes i = bx*8+w (0..2047)
__global__ void prefix_kv_kernel(const float* __restrict__ ct_w2,
                                 const float* __restrict__ ct_b2,
                                 const int*   __restrict__ lang) {
    int wid = threadIdx.x >> 5, lane = threadIdx.x & 31;
    int i = blockIdx.x * 8 + wid;
    int b = blockIdx.y;
    int c = lang[b];
    const float* w = ct_w2 + ((size_t)c * (2 * D_EMB) + i) * BNECK;
    const float* h = g_h + b * BNECK;
    float s = 0.f;
    for (int d = lane; d < BNECK; d += 32) s += w[d] * h[d];
    s = warp_reduce(s);
    if (lane == 0) {
        float val = s + ct_b2[c * (2 * D_EMB) + i];
        int i2 = (i < D_EMB) ? i : i - D_EMB;
        int hh = i2 >> 6, dd = i2 & 63;
        size_t off = ((size_t)(b * NHEAD + hh) * TPAD + 2048) * HDIM + dd;
        if (i < D_EMB) g_k[off] = __float2half_rn(val);
        else           g_v[off] = __float2half_rn(val);
    }
}

// ============ single-fp16 mma.sync GEMM (256x128 tile, 512thr, BK=64) ========
// stage: A 32KB (256 rows x 128B) | B 16KB (128 rows x 128B) = 48KB; 3 stages
#define G_PL_A 0
#define G_PL_B 32768
#define G_STAGE 49152
#define G_SMEM  (3 * G_STAGE)

__global__ __launch_bounds__(512, 1)
void gemm_mma_kernel(const float* __restrict__ b0, const float* __restrict__ b1,
                     const float* __restrict__ b2, float* __restrict__ out,
                     int qkv_mode) {
    extern __shared__ __align__(128) uint8_t smem[];
    uint32_t smb = smem_u32(smem);

    int tid = threadIdx.x, lane = tid & 31, wid = tid >> 5;     // 16 warps
    int z   = qkv_mode ? (int)blockIdx.z : 3;
    int dst = qkv_mode ? z : 3;
    const float* bias = (z == 0 || z == 3) ? b0 : (z == 1) ? b1 : b2;
    float scale = (qkv_mode && z == 0) ? SCAL2 : 1.0f;

    const __half* A = g_x + (size_t)(qkv_mode ? z : 0) * XS;
    const __half* B = g_w[z];

    int m0 = blockIdx.y * 256, n0 = blockIdx.x * 128;
    int wm = (wid >> 2) * 64, wn = (wid & 3) * 32;   // warp tile 64x32

    // loaders: A 2048 cpa16/chunk (4/thread), B 1024 (2/thread)
    int lr0 = tid >> 3, lcc0 = tid & 7;              // lr0 0..63
    uint32_t lsoA[4], lsoB[2];
    const __half *gA[4], *gB[2];
    #pragma unroll
    for (int it = 0; it < 4; it++) {
        int r = lr0 + it * 64;                       // 0..255
        lsoA[it] = swz128(r, lcc0);
        gA[it] = A + (size_t)(m0 + r) * 1024 + lcc0 * 8;
    }
    #pragma unroll
    for (int it = 0; it < 2; it++) {
        int r = lr0 + it * 64;                       // 0..127
        lsoB[it] = swz128(r, lcc0);
        gB[it] = B + (size_t)(n0 + r) * 1024 + lcc0 * 8;
    }

    int laneRowA = lane & 15;
    int ccA = (lane >> 4) & 1;
    int laneRowB = (lane & 7) + ((lane & 16) ? 8 : 0);
    int ccB = (lane >> 3) & 1;

    float c[4][4][4];
    #pragma unroll
    for (int mt = 0; mt < 4; mt++)
        #pragma unroll
        for (int nt = 0; nt < 4; nt++)
            #pragma unroll
            for (int k = 0; k < 4; k++) c[mt][nt][k] = 0.f;

    // prologue: chunks 0,1 -> stages 0,1
    #pragma unroll
    for (int p = 0; p < 2; p++) {
        uint32_t sb = smb + p * G_STAGE;
        int k0 = p * 64;
        #pragma unroll
        for (int it = 0; it < 4; it++) cpa16(sb + G_PL_A + lsoA[it], gA[it] + k0);
        #pragma unroll
        for (int it = 0; it < 2; it++) cpa16(sb + G_PL_B + lsoB[it], gB[it] + k0);
        CP_COMMIT();
    }

    int st = 0, st2 = 2;
    for (int i = 0; i < 16; i++) {
        if (i < 15) { CP_WAIT1(); } else { CP_WAIT0(); }
        __syncthreads();

        uint32_t sb = smb + st * G_STAGE;
        #pragma unroll
        for (int kk = 0; kk < 4; kk++) {
            uint32_t af[4][4], bf[2][4];
            #pragma unroll
            for (int mt = 0; mt < 4; mt++)
                ldsm4(af[mt], sb + G_PL_A + swz128(wm + mt * 16 + laneRowA, kk * 2 + ccA));
            #pragma unroll
            for (int p = 0; p < 2; p++)
                ldsm4(bf[p], sb + G_PL_B + swz128(wn + p * 16 + laneRowB, kk * 2 + ccB));
            #pragma unroll
            for (int mt = 0; mt < 4; mt++) {
                #pragma unroll
                for (int nt = 0; nt < 4; nt++) {
                    int p = nt >> 1, q = (nt & 1) * 2;
                    mma16816(c[mt][nt], af[mt], bf[p][q], bf[p][q + 1]);
                }
            }
        }

        if (i + 2 < 16) {
            uint32_t sb2 = smb + st2 * G_STAGE;
            int k0 = (i + 2) * 64;
            #pragma unroll
            for (int it = 0; it < 4; it++) cpa16(sb2 + G_PL_A + lsoA[it], gA[it] + k0);
            #pragma unroll
            for (int it = 0; it < 2; it++) cpa16(sb2 + G_PL_B + lsoB[it], gB[it] + k0);
            CP_COMMIT();
        }
        st  = (st  == 2) ? 0 : st + 1;
        st2 = (st2 == 2) ? 0 : st2 + 1;
    }

    // epilogue
    int g = lane >> 2, tg = lane & 3;
    #pragma unroll
    for (int mt = 0; mt < 4; mt++) {
        #pragma unroll
        for (int nt = 0; nt < 4; nt++) {
            int n = n0 + wn + nt * 8 + 2 * tg;
            float2 bv = *(const float2*)(bias + n);
            #pragma unroll
            for (int half_ = 0; half_ < 2; half_++) {
                int mg = m0 + wm + mt * 16 + g + half_ * 8;
                float v0 = (c[mt][nt][half_ * 2 + 0] + bv.x) * scale;
                float v1 = (c[mt][nt][half_ * 2 + 1] + bv.y) * scale;
                if (dst == 3) {
                    *(float2*)(out + (size_t)mg * 1024 + n) = make_float2(v0, v1);
                } else {
                    int t_ = mg >> 1, b_ = mg & 1;
                    int hh = n >> 6, dd = n & 63;
                    __half2 hp(__float2half_rn(v0), __float2half_rn(v1));
                    if (dst == 0) {
                        size_t off = ((size_t)(b_ * NHEAD + hh) * T_SEQ + t_) * HDIM + dd;
                        *(__half2*)(g_q + off) = hp;
                    } else {
                        size_t off = ((size_t)(b_ * NHEAD + hh) * TPAD + t_) * HDIM + dd;
                        if (dst == 1) *(__half2*)(g_k + off) = hp;
                        else          *(__half2*)(g_v + off) = hp;
                    }
                }
            }
        }
    }
}

// ================= flash attention, no-max softmax (unchanged) ===============
#define A_K 0
#define A_V 16384
#define A_STAGE 32768
#define A_SMEM  (3 * A_STAGE)

__global__ __launch_bounds__(256, 2)
void attn_mma_kernel() {
    extern __shared__ __align__(128) uint8_t smem[];
    uint32_t smb = smem_u32(smem);

    int tid = threadIdx.x, lane = tid & 31, wid = tid >> 5;
    int qt = blockIdx.x * 128;
    int bh = blockIdx.y;

    const __half* qB = g_q + (size_t)bh * T_SEQ * HDIM;
    const __half* kB = g_k + (size_t)bh * TPAD * HDIM;
    const __half* vB = g_v + (size_t)bh * TPAD * HDIM;

    // ---- stage Q (16KB, single plane) ----
    #pragma unroll
    for (int it = 0; it < 4; it++) {
        int idx = tid + it * 256;
        int r = idx >> 3, cc = idx & 7;
        cpa16(smb + swz128(r, cc), qB + (size_t)(qt + r) * HDIM + cc * 8);
    }
    CP_COMMIT(); CP_WAIT0();
    __syncthreads();

    uint32_t qf[4][4];
    int wrow = wid * 16;
    {
        int r = wrow + (lane & 15);
        int ca = (lane >> 4) & 1;
        #pragma unroll
        for (int j = 0; j < 4; j++)
            ldsm4(qf[j], smb + swz128(r, 2 * j + ca));
    }
    __syncthreads();   // Q consumed; smem free for K/V

    float ctx[8][4];
    #pragma unroll
    for (int nt = 0; nt < 8; nt++)
        #pragma unroll
        for (int k = 0; k < 4; k++) ctx[nt][k] = 0.f;
    float l0 = 0.f, l1 = 0.f;

    int lvr = tid >> 3, lvc = tid & 7;
    uint32_t kvso[4];
    size_t kvg[4];
    #pragma unroll
    for (int it = 0; it < 4; it++) {
        int r = lvr + it * 32;
        kvso[it] = swz128(r, lvc);
        kvg[it] = (size_t)r * HDIM + lvc * 8;
    }

    int laneRowB = (lane & 7) + ((lane & 16) ? 8 : 0);
    int ccB = (lane >> 3) & 1;
    int vLaneRow = ((lane >> 3) & 1) * 8 + (lane & 7);
    int vcc0 = (lane >> 4) & 1;

    #pragma unroll
    for (int p = 0; p < 2; p++) {
        uint32_t sb = smb + p * A_STAGE;
        size_t go = (size_t)p * 128 * HDIM;
        #pragma unroll
        for (int it = 0; it < 4; it++) {
            cpa16(sb + A_K + kvso[it], kB + kvg[it] + go);
            cpa16(sb + A_V + kvso[it], vB + kvg[it] + go);
        }
        CP_COMMIT();
    }

    int st = 0, st2 = 2;
    for (int ci = 0; ci < 17; ci++) {
        if (ci < 16) { CP_WAIT1(); } else { CP_WAIT0(); }
        __syncthreads();

        uint32_t sb = smb + st * A_STAGE;

        #pragma unroll
        for (int hh2 = 0; hh2 < 2; hh2++) {
            int krow = hh2 * 64;

            float s[8][4];
            #pragma unroll
            for (int nt = 0; nt < 8; nt++)
                #pragma unroll
                for (int k = 0; k < 4; k++) s[nt][k] = 0.f;

            #pragma unroll
            for (int j = 0; j < 4; j++) {
                uint32_t kh[4][4];
                #pragma unroll
                for (int p = 0; p < 4; p++)
                    ldsm4(kh[p], sb + A_K + swz128(krow + p * 16 + laneRowB, 2 * j + ccB));
                #pragma unroll
                for (int nt = 0; nt < 8; nt++) {
                    int p = nt >> 1, q = (nt & 1) * 2;
                    mma16816(s[nt], qf[j], kh[p][q], kh[p][q + 1]);
                }
            }

            if (ci == 16) {
                #pragma unroll
                for (int nt = 0; nt < 8; nt++) {
                    int col0 = nt * 8 + 2 * (lane & 3);
                    if (hh2 == 1 || col0 != 0) { s[nt][0] = -1e30f; s[nt][2] = -1e30f; }
                    s[nt][1] = -1e30f; s[nt][3] = -1e30f;
                }
            }

            #pragma unroll
            for (int nt = 0; nt < 8; nt++) {
                s[nt][0] = ex2(s[nt][0]);
                s[nt][1] = ex2(s[nt][1]);
                s[nt][2] = ex2(s[nt][2]);
                s[nt][3] = ex2(s[nt][3]);
                l0 += s[nt][0] + s[nt][1];
                l1 += s[nt][2] + s[nt][3];
            }

            uint32_t pa[4][4];
            #pragma unroll
            for (int jj = 0; jj < 4; jj++) {
                __half2 t0(__float2half_rn(s[2*jj][0]),   __float2half_rn(s[2*jj][1]));
                __half2 t1(__float2half_rn(s[2*jj][2]),   __float2half_rn(s[2*jj][3]));
                __half2 t2(__float2half_rn(s[2*jj+1][0]), __float2half_rn(s[2*jj+1][1]));
                __half2 t3(__float2half_rn(s[2*jj+1][2]), __float2half_rn(s[2*jj+1][3]));
                pa[jj][0] = *(uint32_t*)&t0; pa[jj][1] = *(uint32_t*)&t1;
                pa[jj][2] = *(uint32_t*)&t2; pa[jj][3] = *(uint32_t*)&t3;
            }

            #pragma unroll
            for (int jj = 0; jj < 4; jj++) {
                int vr = krow + jj * 16 + vLaneRow;
                #pragma unroll
                for (int p4 = 0; p4 < 4; p4++) {
                    uint32_t vh[4];
                    ldsm4t(vh, sb + A_V + swz128(vr, p4 * 2 + vcc0));
                    mma16816(ctx[p4 * 2],     pa[jj], vh[0], vh[1]);
                    mma16816(ctx[p4 * 2 + 1], pa[jj], vh[2], vh[3]);
                }
            }
        }

        if (ci + 2 < 17) {
            uint32_t sb2 = smb + st2 * A_STAGE;
            size_t go = (size_t)(ci + 2) * 128 * HDIM;
            #pragma unroll
            for (int it = 0; it < 4; it++) {
                cpa16(sb2 + A_K + kvso[it], kB + kvg[it] + go);
                cpa16(sb2 + A_V + kvso[it], vB + kvg[it] + go);
            }
            CP_COMMIT();
        }
        st  = (st  == 2) ? 0 : st + 1;
        st2 = (st2 == 2) ? 0 : st2 + 1;
    }

    // final row sums + output
    l0 += __shfl_xor_sync(0xffffffffu, l0, 1);
    l0 += __shfl_xor_sync(0xffffffffu, l0, 2);
    l1 += __shfl_xor_sync(0xffffffffu, l1, 1);
    l1 += __shfl_xor_sync(0xffffffffu, l1, 2);
    float inv0 = 1.f / l0, inv1 = 1.f / l1;

    int g = lane >> 2;
    int b = bh >> 4, hh = bh & 15;
    int t0 = qt + wrow + g, t1 = t0 + 8;
    size_t r0 = ((size_t)t0 * BATCH + b) * D_EMB + hh * HDIM;
    size_t r1 = ((size_t)t1 * BATCH + b) * D_EMB + hh * HDIM;
    #pragma unroll
    for (int nt = 0; nt < 8; nt++) {
        int col = nt * 8 + 2 * (lane & 3);
        __half2 h0(__float2half_rn(ctx[nt][0] * inv0), __float2half_rn(ctx[nt][1] * inv0));
        __half2 h1(__float2half_rn(ctx[nt][2] * inv1), __float2half_rn(ctx[nt][3] * inv1));
        *(__half2*)(g_x + r0 + col) = h0;
        *(__half2*)(g_x + r1 + col) = h1;
    }
}

// ---------------- launch ----------------
extern "C" void kernel_launch(void* const* d_in, const int* in_sizes, int n_in,
                              void* d_out, int out_size) {
    const float* query = (const float*)d_in[0];
    const float* key   = (const float*)d_in[1];
    const float* value = (const float*)d_in[2];
    const float* wq    = (const float*)d_in[3];
    const float* bq    = (const float*)d_in[4];
    const float* wk    = (const float*)d_in[5];
    const float* bk    = (const float*)d_in[6];
    const float* wv    = (const float*)d_in[7];
    const float* bv    = (const float*)d_in[8];
    const float* wo    = (const float*)d_in[9];
    const float* bo    = (const float*)d_in[10];
    const float* wte   = (const float*)d_in[11];
    const float* ct_w1 = (const float*)d_in[12];
    const float* ct_b1 = (const float*)d_in[13];
    const float* ct_w2 = (const float*)d_in[14];
    const float* ct_b2 = (const float*)d_in[15];
    const int*   lang  = (const int*)d_in[16];
    float* out = (float*)d_out;

    cudaFuncSetAttribute(gemm_mma_kernel, cudaFuncAttributeMaxDynamicSharedMemorySize, G_SMEM);
    cudaFuncSetAttribute(attn_mma_kernel, cudaFuncAttributeMaxDynamicSharedMemorySize, A_SMEM);

    conv_all_kernel<<<dim3(XS / 4 / 256, 7), 256>>>(query, key, value, wq, wk, wv, wo);

    prefix_h_kernel<<<dim3(100, BATCH), 256>>>(wte, ct_w1, ct_b1, lang);
    prefix_kv_kernel<<<dim3(256, BATCH), 256>>>(ct_w2, ct_b2, lang);

    // fused QKV projections: 256x128 tiles
    gemm_mma_kernel<<<dim3(8, 16, 3), 512, G_SMEM>>>(bq, bk, bv, nullptr, 1);

    attn_mma_kernel<<<dim3(T_SEQ / 128, BATCH * NHEAD), 256, A_SMEM>>>();

    gemm_mma_kernel<<<dim3(8, 16, 1), 512, G_SMEM>>>(bo, nullptr, nullptr, out, 0);
}

// round 14
// speedup vs baseline: 1.0693x; 1.0693x over previous
#include <cuda_runtime.h>
#include <cuda_fp16.h>
#include <math.h>
#include <stdint.h>

// ---------------- problem constants ----------------
#define T_SEQ   2048
#define BATCH   2
#define D_EMB   1024
#define NHEAD   16
#define HDIM    64
#define BNECK   800
#define LOG2E   1.4426950408889634f
#define SCAL2   (0.125f * LOG2E)     // folded into Q projection; softmax uses exp2
#define TPAD    2176                 // 17 chunks * 128 keys; prefix row at 2048
#define XS      (4096 * 1024)        // one input-plane slot (elements)

// ---------------- scratch (device globals; zero-initialized) ----------------
__device__ float g_h[BATCH * BNECK];

// single fp16 planes. g_x slots: 0=query/ctx, 1=key, 2=value
__device__ __half g_x[3 * XS];
__device__ __half g_w[4][1024 * 1024];                 // wq,wk,wv,wo
__device__ __half g_q [BATCH * NHEAD * T_SEQ * HDIM];
__device__ __half g_k [BATCH * NHEAD * TPAD * HDIM];   // rows 2049.. stay zero
__device__ __half g_v [BATCH * NHEAD * TPAD * HDIM];

// ---------------- helpers ----------------
__device__ __forceinline__ uint32_t smem_u32(const void* p) {
    uint32_t a;
    asm("{ .reg .u64 t; cvta.to.shared.u64 t, %1; cvt.u32.u64 %0, t; }" : "=r"(a) : "l"(p));
    return a;
}
__device__ __forceinline__ void ldsm4(uint32_t* r, uint32_t a) {
    asm volatile("ldmatrix.sync.aligned.m8n8.x4.shared.b16 {%0,%1,%2,%3}, [%4];"
                 : "=r"(r[0]), "=r"(r[1]), "=r"(r[2]), "=r"(r[3]) : "r"(a));
}
__device__ __forceinline__ void ldsm4t(uint32_t* r, uint32_t a) {
    asm volatile("ldmatrix.sync.aligned.m8n8.x4.trans.shared.b16 {%0,%1,%2,%3}, [%4];"
                 : "=r"(r[0]), "=r"(r[1]), "=r"(r[2]), "=r"(r[3]) : "r"(a));
}
__device__ __forceinline__ void mma16816(float* c, const uint32_t* a, uint32_t b0, uint32_t b1) {
    asm volatile("mma.sync.aligned.m16n8k16.row.col.f32.f16.f16.f32 "
                 "{%0,%1,%2,%3}, {%4,%5,%6,%7}, {%8,%9}, {%0,%1,%2,%3};"
                 : "+f"(c[0]), "+f"(c[1]), "+f"(c[2]), "+f"(c[3])
                 : "r"(a[0]), "r"(a[1]), "r"(a[2]), "r"(a[3]), "r"(b0), "r"(b1));
}
__device__ __forceinline__ void cpa16(uint32_t sdst, const void* gsrc) {
    asm volatile("cp.async.cg.shared.global [%0], [%1], 16;" :: "r"(sdst), "l"(gsrc));
}
#define CP_COMMIT() asm volatile("cp.async.commit_group;" ::: "memory")
#define CP_WAIT1()  asm volatile("cp.async.wait_group 1;" ::: "memory")
#define CP_WAIT0()  asm volatile("cp.async.wait_group 0;" ::: "memory")

__device__ __forceinline__ float ex2(float x) {
    float y;
    asm("ex2.approx.ftz.f32 %0, %1;" : "=f"(y) : "f"(x));
    return y;
}

// 128B-row swizzle (8 chunks of 16B per row)
__device__ __forceinline__ uint32_t swz128(int r, int cc) {
    return (uint32_t)(r * 128 + ((cc ^ (r & 7)) << 4));
}

__device__ __forceinline__ float warp_reduce(float v) {
    #pragma unroll
    for (int o = 16; o; o >>= 1) v += __shfl_xor_sync(0xffffffffu, v, o);
    return v;
}

// ---------------- merged conversion: 3 inputs + 4 weights ----------------
__global__ void conv_all_kernel(const float* __restrict__ q, const float* __restrict__ k,
                                const float* __restrict__ v, const float* __restrict__ w0,
                                const float* __restrict__ w1, const float* __restrict__ w2,
                                const float* __restrict__ w3) {
    int slot = blockIdx.y;
    const float* src;
    __half* dstp;
    if (slot < 3) {
        src = (slot == 0) ? q : (slot == 1) ? k : v;
        dstp = g_x + (size_t)slot * XS;
    } else {
        if (blockIdx.x >= 1024) return;
        int ws = slot - 3;
        src = (ws == 0) ? w0 : (ws == 1) ? w1 : (ws == 2) ? w2 : w3;
        dstp = g_w[ws];
    }
    int i = blockIdx.x * 256 + threadIdx.x;
    float4 val = ((const float4*)src)[i];
    __half2* pd = (__half2*)dstp;
    pd[i * 2 + 0] = __half2(__float2half_rn(val.x), __float2half_rn(val.y));
    pd[i * 2 + 1] = __half2(__float2half_rn(val.z), __float2half_rn(val.w));
}

// ---------------- prefix MLP (warp-per-output) ----------------
// grid (100, BATCH), block 256 (8 warps); warp w computes j = bx*8+w
__global__ void prefix_h_kernel(const float* __restrict__ wte,
                                const float* __restrict__ ct_w1,
                                const float* __restrict__ ct_b1,
                                const int*   __restrict__ lang) {
    int wid = threadIdx.x >> 5, lane = threadIdx.x & 31;
    int j = blockIdx.x * 8 + wid;
    int b = blockIdx.y;
    int c = lang[b];
    const float* w = ct_w1 + ((size_t)c * BNECK + j) * D_EMB;
    const float* e = wte + (size_t)c * D_EMB;
    float s = 0.f;
    #pragma unroll
    for (int it = 0; it < 8; it++) {
        float4 wv = *(const float4*)(w + (lane + it * 32) * 4);
        float4 ev = *(const float4*)(e + (lane + it * 32) * 4);
        s += wv.x * ev.x + wv.y * ev.y + wv.z * ev.z + wv.w * ev.w;
    }
    s = warp_reduce(s);
    if (lane == 0)
        g_h[b * BNECK + j] = tanhf(s + ct_b1[c * BNECK + j]);
}

// grid (256, BATCH), block 256; warp w computes i = bx*8+w (0..2047)
__global__ void prefix_kv_kernel(const float* __restrict__ ct_w2,
                                 const float* __restrict__ ct_b2,
                                 const int*   __restrict__ lang) {
    int wid = threadIdx.x >> 5, lane = threadIdx.x & 31;
    int i = blockIdx.x * 8 + wid;
    int b = blockIdx.y;
    int c = lang[b];
    const float* w = ct_w2 + ((size_t)c * (2 * D_EMB) + i) * BNECK;
    const float* h = g_h + b * BNECK;
    float s = 0.f;
    for (int d = lane; d < BNECK; d += 32) s += w[d] * h[d];
    s = warp_reduce(s);
    if (lane == 0) {
        float val = s + ct_b2[c * (2 * D_EMB) + i];
        int i2 = (i < D_EMB) ? i : i - D_EMB;
        int hh = i2 >> 6, dd = i2 & 63;
        size_t off = ((size_t)(b * NHEAD + hh) * TPAD + 2048) * HDIM + dd;
        if (i < D_EMB) g_k[off] = __float2half_rn(val);
        else           g_v[off] = __float2half_rn(val);
    }
}

// ============ single-fp16 mma.sync GEMM (R12 config: 128x128, 256thr, occ2) ==
// stage: A 16KB | B 16KB = 32KB ; 3 stages = 96KB dynamic
#define G_PL_A 0
#define G_PL_B 16384
#define G_STAGE 32768
#define G_SMEM  (3 * G_STAGE)

__global__ __launch_bounds__(256, 2)
void gemm_mma_kernel(const float* __restrict__ b0, const float* __restrict__ b1,
                     const float* __restrict__ b2, float* __restrict__ out,
                     int qkv_mode) {
    extern __shared__ __align__(128) uint8_t smem[];
    uint32_t smb = smem_u32(smem);

    int tid = threadIdx.x, lane = tid & 31, wid = tid >> 5;
    int z   = qkv_mode ? (int)blockIdx.z : 3;
    int dst = qkv_mode ? z : 3;
    const float* bias = (z == 0 || z == 3) ? b0 : (z == 1) ? b1 : b2;
    float scale = (qkv_mode && z == 0) ? SCAL2 : 1.0f;

    const __half* A = g_x + (size_t)(qkv_mode ? z : 0) * XS;
    const __half* B = g_w[z];

    int m0 = blockIdx.y * 128, n0 = blockIdx.x * 128;
    int wm = (wid >> 2) * 64, wn = (wid & 3) * 32;

    int lr0 = tid >> 3, lcc0 = tid & 7;
    uint32_t lso[4];
    const __half *gA[4], *gB[4];
    #pragma unroll
    for (int it = 0; it < 4; it++) {
        int r = lr0 + it * 32;
        lso[it] = swz128(r, lcc0);
        gA[it] = A + (size_t)(m0 + r) * 1024 + lcc0 * 8;
        gB[it] = B + (size_t)(n0 + r) * 1024 + lcc0 * 8;
    }

    int laneRowA = lane & 15;
    int ccA = (lane >> 4) & 1;
    int laneRowB = (lane & 7) + ((lane & 16) ? 8 : 0);
    int ccB = (lane >> 3) & 1;

    float c[4][4][4];
    #pragma unroll
    for (int mt = 0; mt < 4; mt++)
        #pragma unroll
        for (int nt = 0; nt < 4; nt++)
            #pragma unroll
            for (int k = 0; k < 4; k++) c[mt][nt][k] = 0.f;

    #pragma unroll
    for (int p = 0; p < 2; p++) {
        uint32_t sb = smb + p * G_STAGE;
        int k0 = p * 64;
        #pragma unroll
        for (int it = 0; it < 4; it++) {
            cpa16(sb + G_PL_A + lso[it], gA[it] + k0);
            cpa16(sb + G_PL_B + lso[it], gB[it] + k0);
        }
        CP_COMMIT();
    }

    int st = 0, st2 = 2;
    for (int i = 0; i < 16; i++) {
        if (i < 15) { CP_WAIT1(); } else { CP_WAIT0(); }
        __syncthreads();

        uint32_t sb = smb + st * G_STAGE;
        #pragma unroll
        for (int kk = 0; kk < 4; kk++) {
            uint32_t af[4][4], bf[2][4];
            #pragma unroll
            for (int mt = 0; mt < 4; mt++)
                ldsm4(af[mt], sb + G_PL_A + swz128(wm + mt * 16 + laneRowA, kk * 2 + ccA));
            #pragma unroll
            for (int p = 0; p < 2; p++)
                ldsm4(bf[p], sb + G_PL_B + swz128(wn + p * 16 + laneRowB, kk * 2 + ccB));
            #pragma unroll
            for (int mt = 0; mt < 4; mt++) {
                #pragma unroll
                for (int nt = 0; nt < 4; nt++) {
                    int p = nt >> 1, q = (nt & 1) * 2;
                    mma16816(c[mt][nt], af[mt], bf[p][q], bf[p][q + 1]);
                }
            }
        }

        if (i + 2 < 16) {
            uint32_t sb2 = smb + st2 * G_STAGE;
            int k0 = (i + 2) * 64;
            #pragma unroll
            for (int it = 0; it < 4; it++) {
                cpa16(sb2 + G_PL_A + lso[it], gA[it] + k0);
                cpa16(sb2 + G_PL_B + lso[it], gB[it] + k0);
            }
            CP_COMMIT();
        }
        st  = (st  == 2) ? 0 : st + 1;
        st2 = (st2 == 2) ? 0 : st2 + 1;
    }

    // epilogue
    int g = lane >> 2, tg = lane & 3;
    #pragma unroll
    for (int mt = 0; mt < 4; mt++) {
        #pragma unroll
        for (int nt = 0; nt < 4; nt++) {
            int n = n0 + wn + nt * 8 + 2 * tg;
            float2 bv = *(const float2*)(bias + n);
            #pragma unroll
            for (int half_ = 0; half_ < 2; half_++) {
                int mg = m0 + wm + mt * 16 + g + half_ * 8;
                float v0 = (c[mt][nt][half_ * 2 + 0] + bv.x) * scale;
                float v1 = (c[mt][nt][half_ * 2 + 1] + bv.y) * scale;
                if (dst == 3) {
                    *(float2*)(out + (size_t)mg * 1024 + n) = make_float2(v0, v1);
                } else {
                    int t_ = mg >> 1, b_ = mg & 1;
                    int hh = n >> 6, dd = n & 63;
                    __half2 hp(__float2half_rn(v0), __float2half_rn(v1));
                    if (dst == 0) {
                        size_t off = ((size_t)(b_ * NHEAD + hh) * T_SEQ + t_) * HDIM + dd;
                        *(__half2*)(g_q + off) = hp;
                    } else {
                        size_t off = ((size_t)(b_ * NHEAD + hh) * TPAD + t_) * HDIM + dd;
                        if (dst == 1) *(__half2*)(g_k + off) = hp;
                        else          *(__half2*)(g_v + off) = hp;
                    }
                }
            }
        }
    }
}

// ================= flash attention, no-max softmax ===========================
// stage: K 16KB | V 16KB = 32KB ; 3 stages = 96KB dynamic
#define A_K 0
#define A_V 16384
#define A_STAGE 32768
#define A_SMEM  (3 * A_STAGE)

__global__ __launch_bounds__(256, 2)
void attn_mma_kernel() {
    extern __shared__ __align__(128) uint8_t smem[];
    uint32_t smb = smem_u32(smem);

    int tid = threadIdx.x, lane = tid & 31, wid = tid >> 5;
    int qt = blockIdx.x * 128;
    int bh = blockIdx.y;

    const __half* qB = g_q + (size_t)bh * T_SEQ * HDIM;
    const __half* kB = g_k + (size_t)bh * TPAD * HDIM;
    const __half* vB = g_v + (size_t)bh * TPAD * HDIM;

    // ---- stage Q (16KB, single plane) ----
    #pragma unroll
    for (int it = 0; it < 4; it++) {
        int idx = tid + it * 256;
        int r = idx >> 3, cc = idx & 7;
        cpa16(smb + swz128(r, cc), qB + (size_t)(qt + r) * HDIM + cc * 8);
    }
    CP_COMMIT(); CP_WAIT0();
    __syncthreads();

    uint32_t qf[4][4];
    int wrow = wid * 16;
    {
        int r = wrow + (lane & 15);
        int ca = (lane >> 4) & 1;
        #pragma unroll
        for (int j = 0; j < 4; j++)
            ldsm4(qf[j], smb + swz128(r, 2 * j + ca));
    }
    __syncthreads();   // Q consumed; smem free for K/V

    float ctx[8][4];
    #pragma unroll
    for (int nt = 0; nt < 8; nt++)
        #pragma unroll
        for (int k = 0; k < 4; k++) ctx[nt][k] = 0.f;
    float l0 = 0.f, l1 = 0.f;

    int lvr = tid >> 3, lvc = tid & 7;
    uint32_t kvso[4];
    size_t kvg[4];
    #pragma unroll
    for (int it = 0; it < 4; it++) {
        int r = lvr + it * 32;
        kvso[it] = swz128(r, lvc);
        kvg[it] = (size_t)r * HDIM + lvc * 8;
    }

    int laneRowB = (lane & 7) + ((lane & 16) ? 8 : 0);
    int ccB = (lane >> 3) & 1;
    int vLaneRow = ((lane >> 3) & 1) * 8 + (lane & 7);
    int vcc0 = (lane >> 4) & 1;

    #pragma unroll
    for (int p = 0; p < 2; p++) {
        uint32_t sb = smb + p * A_STAGE;
        size_t go = (size_t)p * 128 * HDIM;
        #pragma unroll
        for (int it = 0; it < 4; it++) {
            cpa16(sb + A_K + kvso[it], kB + kvg[it] + go);
            cpa16(sb + A_V + kvso[it], vB + kvg[it] + go);
        }
        CP_COMMIT();
    }

    int st = 0, st2 = 2;
    for (int ci = 0; ci < 17; ci++) {
        if (ci < 16) { CP_WAIT1(); } else { CP_WAIT0(); }
        __syncthreads();

        uint32_t sb = smb + st * A_STAGE;
        int nsub = (ci == 16) ? 1 : 2;     // last chunk: sub-block 1 fully masked, skip

        for (int hh2 = 0; hh2 < nsub; hh2++) {
            int krow = hh2 * 64;

            float s[8][4];
            #pragma unroll
            for (int nt = 0; nt < 8; nt++)
                #pragma unroll
                for (int k = 0; k < 4; k++) s[nt][k] = 0.f;

            #pragma unroll
            for (int j = 0; j < 4; j++) {
                uint32_t kh[4][4];
                #pragma unroll
                for (int p = 0; p < 4; p++)
                    ldsm4(kh[p], sb + A_K + swz128(krow + p * 16 + laneRowB, 2 * j + ccB));
                #pragma unroll
                for (int nt = 0; nt < 8; nt++) {
                    int p = nt >> 1, q = (nt & 1) * 2;
                    mma16816(s[nt], qf[j], kh[p][q], kh[p][q + 1]);
                }
            }

            // mask: last chunk sub-block 0: only key 2048 (local col 0) valid
            if (ci == 16) {
                #pragma unroll
                for (int nt = 0; nt < 8; nt++) {
                    int col0 = nt * 8 + 2 * (lane & 3);
                    if (col0 != 0) { s[nt][0] = -1e30f; s[nt][2] = -1e30f; }
                    s[nt][1] = -1e30f; s[nt][3] = -1e30f;
                }
            }

            // softmax, no max subtraction (scores bounded; exp2 safe)
            #pragma unroll
            for (int nt = 0; nt < 8; nt++) {
                s[nt][0] = ex2(s[nt][0]);
                s[nt][1] = ex2(s[nt][1]);
                s[nt][2] = ex2(s[nt][2]);
                s[nt][3] = ex2(s[nt][3]);
                l0 += s[nt][0] + s[nt][1];
                l1 += s[nt][2] + s[nt][3];
            }

            uint32_t pa[4][4];
            #pragma unroll
            for (int jj = 0; jj < 4; jj++) {
                __half2 t0(__float2half_rn(s[2*jj][0]),   __float2half_rn(s[2*jj][1]));
                __half2 t1(__float2half_rn(s[2*jj][2]),   __float2half_rn(s[2*jj][3]));
                __half2 t2(__float2half_rn(s[2*jj+1][0]), __float2half_rn(s[2*jj+1][1]));
                __half2 t3(__float2half_rn(s[2*jj+1][2]), __float2half_rn(s[2*jj+1][3]));
                pa[jj][0] = *(uint32_t*)&t0; pa[jj][1] = *(uint32_t*)&t1;
                pa[jj][2] = *(uint32_t*)&t2; pa[jj][3] = *(uint32_t*)&t3;
            }

            #pragma unroll
            for (int jj = 0; jj < 4; jj++) {
                int vr = krow + jj * 16 + vLaneRow;
                #pragma unroll
                for (int p4 = 0; p4 < 4; p4++) {
                    uint32_t vh[4];
                    ldsm4t(vh, sb + A_V + swz128(vr, p4 * 2 + vcc0));
                    mma16816(ctx[p4 * 2],     pa[jj], vh[0], vh[1]);
                    mma16816(ctx[p4 * 2 + 1], pa[jj], vh[2], vh[3]);
                }
            }
        }

        if (ci + 2 < 17) {
            uint32_t sb2 = smb + st2 * A_STAGE;
            size_t go = (size_t)(ci + 2) * 128 * HDIM;
            #pragma unroll
            for (int it = 0; it < 4; it++) {
                cpa16(sb2 + A_K + kvso[it], kB + kvg[it] + go);
                cpa16(sb2 + A_V + kvso[it], vB + kvg[it] + go);
            }
            CP_COMMIT();
        }
        st  = (st  == 2) ? 0 : st + 1;
        st2 = (st2 == 2) ? 0 : st2 + 1;
    }

    // final row sums + output
    l0 += __shfl_xor_sync(0xffffffffu, l0, 1);
    l0 += __shfl_xor_sync(0xffffffffu, l0, 2);
    l1 += __shfl_xor_sync(0xffffffffu, l1, 1);
    l1 += __shfl_xor_sync(0xffffffffu, l1, 2);
    float inv0 = 1.f / l0, inv1 = 1.f / l1;

    int g = lane >> 2;
    int b = bh >> 4, hh = bh & 15;
    int t0 = qt + wrow + g, t1 = t0 + 8;
    size_t r0 = ((size_t)t0 * BATCH + b) * D_EMB + hh * HDIM;
    size_t r1 = ((size_t)t1 * BATCH + b) * D_EMB + hh * HDIM;
    #pragma unroll
    for (int nt = 0; nt < 8; nt++) {
        int col = nt * 8 + 2 * (lane & 3);
        __half2 h0(__float2half_rn(ctx[nt][0] * inv0), __float2half_rn(ctx[nt][1] * inv0));
        __half2 h1(__float2half_rn(ctx[nt][2] * inv1), __float2half_rn(ctx[nt][3] * inv1));
        *(__half2*)(g_x + r0 + col) = h0;
        *(__half2*)(g_x + r1 + col) = h1;
    }
}

// ---------------- launch ----------------
extern "C" void kernel_launch(void* const* d_in, const int* in_sizes, int n_in,
                              void* d_out, int out_size) {
    const float* query = (const float*)d_in[0];
    const float* key   = (const float*)d_in[1];
    const float* value = (const float*)d_in[2];
    const float* wq    = (const float*)d_in[3];
    const float* bq    = (const float*)d_in[4];
    const float* wk    = (const float*)d_in[5];
    const float* bk    = (const float*)d_in[6];
    const float* wv    = (const float*)d_in[7];
    const float* bv    = (const float*)d_in[8];
    const float* wo    = (const float*)d_in[9];
    const float* bo    = (const float*)d_in[10];
    const float* wte   = (const float*)d_in[11];
    const float* ct_w1 = (const float*)d_in[12];
    const float* ct_b1 = (const float*)d_in[13];
    const float* ct_w2 = (const float*)d_in[14];
    const float* ct_b2 = (const float*)d_in[15];
    const int*   lang  = (const int*)d_in[16];
    float* out = (float*)d_out;

    cudaFuncSetAttribute(gemm_mma_kernel, cudaFuncAttributeMaxDynamicSharedMemorySize, G_SMEM);
    cudaFuncSetAttribute(attn_mma_kernel, cudaFuncAttributeMaxDynamicSharedMemorySize, A_SMEM);

    conv_all_kernel<<<dim3(XS / 4 / 256, 7), 256>>>(query, key, value, wq, wk, wv, wo);

    prefix_h_kernel<<<dim3(100, BATCH), 256>>>(wte, ct_w1, ct_b1, lang);
    prefix_kv_kernel<<<dim3(256, BATCH), 256>>>(ct_w2, ct_b2, lang);

    // fused QKV projections (R12 config: 128x128 tiles, occ 2)
    gemm_mma_kernel<<<dim3(8, 32, 3), 256, G_SMEM>>>(bq, bk, bv, nullptr, 1);

    attn_mma_kernel<<<dim3(T_SEQ / 128, BATCH * NHEAD), 256, A_SMEM>>>();

    gemm_mma_kernel<<<dim3(8, 32, 1), 256, G_SMEM>>>(bo, nullptr, nullptr, out, 0);
}